// round 2
// baseline (speedup 1.0000x reference)
#include <cuda_runtime.h>
#include <cuda_bf16.h>
#include <math.h>

// ---------------------------------------------------------------------------
// Decoder: conv3x3(256->128) -> deform_conv(offset conv + bilinear sample +
// 9-tap GEMM) -> conv3x3(128->128) -> BN -> exact GELU -> mask conv(128->1)
// B=8, C=128, H=W=56.  Internal layout: NHWC (channel-contiguous) so the
// deformable gather reads contiguous 512B vectors.  Output: h in NCHW
// (3,211,264 floats) then mask (25,088 floats).
// ---------------------------------------------------------------------------

#define H 56
#define W 56
#define B 8
#define C 128
#define NPIX 3136          // 56*56
#define NTOT 25088         // B*NPIX

// ---- scratch (static __device__ — no allocation allowed) ----
__device__ float g_xy [NTOT * 256];   // concat(x,y) NHWC
__device__ float g_h1 [NTOT * 128];   // conv1 out NHWC
__device__ float g_off[NTOT * 32];    // offsets NHWC (18 real, padded 32)
__device__ float g_h2 [NTOT * 128];   // deform out NHWC
__device__ float g_h3 [NTOT * 128];   // conv2 out NHWC
__device__ float g_w1t [256 * 9 * 128]; // [ci][k][co]
__device__ float g_offwt[128 * 9 * 32]; // [ci][k][co(pad32)]
__device__ float g_w2t [128 * 9 * 128];
__device__ float g_dcnt[9 * 128 * 128]; // [tap][ci][co]
__device__ float g_sum[128], g_sq[128], g_scale[128], g_shift[128];

template<int TAG> __device__ __forceinline__ float* bufp() {
    if constexpr (TAG == 0) return g_xy;
    else if constexpr (TAG == 1) return g_h1;
    else if constexpr (TAG == 2) return g_off;
    else if constexpr (TAG == 3) return g_h2;
    else return g_h3;
}
template<int TAG> __device__ __forceinline__ const float* wbufp() {
    if constexpr (TAG == 0) return g_w1t;
    else if constexpr (TAG == 1) return g_offwt;
    else return g_w2t;
}

// ---------------------------------------------------------------------------
// prep: transpose all conv weights to [ci][k][co] (co contiguous), zero stats
// ---------------------------------------------------------------------------
__global__ void prep_kernel(const float* __restrict__ w1, const float* __restrict__ ow,
                            const float* __restrict__ w2, const float* __restrict__ dw) {
    int idx = blockIdx.x * blockDim.x + threadIdx.x;
    int stride = gridDim.x * blockDim.x;
    for (int i = idx; i < 256 * 9 * 128; i += stride) {
        int co = i % 128, k = (i / 128) % 9, ci = i / 1152;
        g_w1t[i] = w1[(co * 256 + ci) * 9 + k];
    }
    for (int i = idx; i < 128 * 9 * 32; i += stride) {
        int co = i % 32, k = (i / 32) % 9, ci = i / 288;
        g_offwt[i] = (co < 18) ? ow[(co * 128 + ci) * 9 + k] : 0.f;
    }
    for (int i = idx; i < 128 * 9 * 128; i += stride) {
        int co = i % 128, k = (i / 128) % 9, ci = i / 1152;
        g_w2t[i] = w2[(co * 128 + ci) * 9 + k];
    }
    for (int i = idx; i < 9 * 128 * 128; i += stride) {
        int co = i % 128, ci = (i / 128) % 128, k = i / 16384;
        g_dcnt[i] = dw[(co * 128 + ci) * 9 + k];
    }
    for (int i = idx; i < 128; i += stride) { g_sum[i] = 0.f; g_sq[i] = 0.f; }
}

// ---------------------------------------------------------------------------
// NCHW -> NHWC transpose of x and y into g_xy (concat on channel)
// ---------------------------------------------------------------------------
__global__ void transpose_in_kernel(const float* __restrict__ x, const float* __restrict__ y) {
    __shared__ float s[64 * 129];
    int tid = threadIdx.x;
    int b = blockIdx.y;
    int p0 = blockIdx.x * 64;
    #pragma unroll
    for (int src = 0; src < 2; src++) {
        const float* in = src ? y : x;
        for (int idx = tid; idx < 64 * 128; idx += 256) {
            int c = idx >> 6, p = idx & 63;
            s[p * 129 + c] = in[(b * 128 + c) * NPIX + p0 + p];
        }
        __syncthreads();
        for (int idx = tid; idx < 64 * 128; idx += 256) {
            int p = idx >> 7, c = idx & 127;
            g_xy[(b * NPIX + p0 + p) * 256 + src * 128 + c] = s[p * 129 + c];
        }
        __syncthreads();
    }
}

// ---------------------------------------------------------------------------
// Generic 3x3 SAME conv, NHWC.  Tile 8x8 spatial, CO_T couts per block.
// Thread reg tile: 4 couts x 4 pixels.  smem padded against bank conflicts.
// ---------------------------------------------------------------------------
template<int CI, int CO_T, int COP, int CO_REAL, int INB, int OUTB, int WB>
__global__ void conv3x3_kernel(const float* __restrict__ bias) {
    constexpr int NTHR = (CO_T / 4) * 16;
    __shared__ float in_s[8 * 110];        // [ci][py*11+px], row pad 11
    __shared__ float w_s[8 * 9 * CO_T];    // [ci][k][co]

    const float* __restrict__ in  = bufp<INB>();
    float* __restrict__ out       = bufp<OUTB>();
    const float* __restrict__ wt  = wbufp<WB>();

    int tid = threadIdx.x;
    int ty = blockIdx.x / 7, tx = blockIdx.x % 7;
    int b = blockIdx.z;
    int cob = blockIdx.y * CO_T;
    int pg = tid & 15, cg = tid >> 4;
    int r = pg >> 1, cb = (pg & 1) * 4;
    int co_base = cg * 4;
    int y0g = ty * 8 - 1, x0g = tx * 8 - 1;

    float acc[4][4];
    #pragma unroll
    for (int i = 0; i < 4; i++)
        #pragma unroll
        for (int j = 0; j < 4; j++) acc[i][j] = 0.f;

    for (int cc = 0; cc < CI / 8; cc++) {
        __syncthreads();
        // input chunk: 10x10 halo x 8 channels
        for (int idx = tid; idx < 800; idx += NTHR) {
            int pix = idx >> 3, ci = idx & 7;
            int py = pix / 10, px = pix % 10;
            int gy = y0g + py, gx = x0g + px;
            float v = 0.f;
            if (gy >= 0 && gy < H && gx >= 0 && gx < W)
                v = in[((b * H + gy) * W + gx) * CI + cc * 8 + ci];
            in_s[ci * 110 + py * 11 + px] = v;
        }
        // weight chunk: [8 ci][9 k][CO_T co]
        constexpr int WV = 8 * 9 * CO_T / 4;
        for (int i = tid; i < WV; i += NTHR) {
            int co4 = (i % (CO_T / 4)) * 4;
            int rest = i / (CO_T / 4);
            int k = rest % 9, ci = rest / 9;
            *(float4*)&w_s[(ci * 9 + k) * CO_T + co4] =
                *(const float4*)&wt[((cc * 8 + ci) * 9 + k) * COP + cob + co4];
        }
        __syncthreads();

        #pragma unroll
        for (int ci = 0; ci < 8; ci++) {
            #pragma unroll
            for (int ky = 0; ky < 3; ky++) {
                #pragma unroll
                for (int kx = 0; kx < 3; kx++) {
                    float4 wv = *(float4*)&w_s[(ci * 9 + ky * 3 + kx) * CO_T + co_base];
                    const float* ip = &in_s[ci * 110 + (r + ky) * 11 + cb + kx];
                    float i0 = ip[0], i1 = ip[1], i2 = ip[2], i3 = ip[3];
                    acc[0][0] += wv.x * i0; acc[0][1] += wv.x * i1; acc[0][2] += wv.x * i2; acc[0][3] += wv.x * i3;
                    acc[1][0] += wv.y * i0; acc[1][1] += wv.y * i1; acc[1][2] += wv.y * i2; acc[1][3] += wv.y * i3;
                    acc[2][0] += wv.z * i0; acc[2][1] += wv.z * i1; acc[2][2] += wv.z * i2; acc[2][3] += wv.z * i3;
                    acc[3][0] += wv.w * i0; acc[3][1] += wv.w * i1; acc[3][2] += wv.w * i2; acc[3][3] += wv.w * i3;
                }
            }
        }
    }

    float bv[4];
    #pragma unroll
    for (int c = 0; c < 4; c++) {
        int co = cob + co_base + c;
        bv[c] = (co < CO_REAL) ? bias[co] : 0.f;
    }
    #pragma unroll
    for (int j = 0; j < 4; j++) {
        int gy = ty * 8 + r, gx = tx * 8 + cb + j;
        float4 o = make_float4(acc[0][j] + bv[0], acc[1][j] + bv[1],
                               acc[2][j] + bv[2], acc[3][j] + bv[3]);
        *(float4*)&out[((b * H + gy) * W + gx) * COP + cob + co_base] = o;
    }
}

// ---------------------------------------------------------------------------
// Deformable conv: 4x4 pixel tile per block.
// Phase 1: bilinear-sample 9 taps x 128 ci into smem (16*1153 floats, padded).
// Phase 2: GEMM sampled[16][1152] x dcn_t[1152][128] -> h2.
// Weight staged in 32-ci chunks (16KB) to halve barrier count.
// ---------------------------------------------------------------------------
#define DEF_SAMP_FLOATS (16 * 1153)
#define DEF_WCHUNK (32 * 128)
#define DEF_SMEM_BYTES ((DEF_SAMP_FLOATS + DEF_WCHUNK) * 4)

__global__ void deform_kernel(const float* __restrict__ dcn_b) {
    extern __shared__ float dsm[];
    float* samp = dsm;
    float* w_s  = dsm + DEF_SAMP_FLOATS;

    int tid = threadIdx.x;
    int b = blockIdx.z;
    int ty = blockIdx.x / 14, tx = blockIdx.x % 14;

    // ---- phase 1: gather ----
    int wid = tid >> 5, lane = tid & 31;
    for (int t = wid; t < 144; t += 8) {
        int pl = t / 9, tap = t % 9;
        int rr = pl >> 2, cl = pl & 3;
        int y = ty * 4 + rr, x = tx * 4 + cl;
        const float* ob = &g_off[((b * H + y) * W + x) * 32];
        float offy = ob[2 * tap], offx = ob[2 * tap + 1];
        float py = (float)y + (float)(tap / 3 - 1) + offy;
        float px = (float)x + (float)(tap % 3 - 1) + offx;
        float y0 = floorf(py), x0 = floorf(px);
        float y1 = y0 + 1.f, x1 = x0 + 1.f;
        float wy1 = py - y0, wy0 = 1.f - wy1;
        float wx1 = px - x0, wx0 = 1.f - wx1;
        float vy0 = (y0 >= 0.f && y0 <= 55.f) ? 1.f : 0.f;
        float vy1 = (y1 >= 0.f && y1 <= 55.f) ? 1.f : 0.f;
        float vx0 = (x0 >= 0.f && x0 <= 55.f) ? 1.f : 0.f;
        float vx1 = (x1 >= 0.f && x1 <= 55.f) ? 1.f : 0.f;
        float w00 = wy0 * wx0 * vy0 * vx0;
        float w01 = wy0 * wx1 * vy0 * vx1;
        float w10 = wy1 * wx0 * vy1 * vx0;
        float w11 = wy1 * wx1 * vy1 * vx1;
        int iy0 = (int)fminf(fmaxf(y0, 0.f), 55.f);
        int iy1 = (int)fminf(fmaxf(y1, 0.f), 55.f);
        int ix0 = (int)fminf(fmaxf(x0, 0.f), 55.f);
        int ix1 = (int)fminf(fmaxf(x1, 0.f), 55.f);
        const float* p00 = &g_h1[((b * H + iy0) * W + ix0) * 128];
        const float* p01 = &g_h1[((b * H + iy0) * W + ix1) * 128];
        const float* p10 = &g_h1[((b * H + iy1) * W + ix0) * 128];
        const float* p11 = &g_h1[((b * H + iy1) * W + ix1) * 128];
        float* sp = &samp[pl * 1153 + tap * 128];
        #pragma unroll
        for (int q = 0; q < 4; q++) {
            int ci = lane + q * 32;
            sp[ci] = w00 * p00[ci] + w01 * p01[ci] + w10 * p10[ci] + w11 * p11[ci];
        }
    }
    __syncthreads();

    // ---- phase 2: GEMM ----
    int pxl = tid & 15, cg = tid >> 4;
    int co0 = cg * 8;
    float acc[8];
    #pragma unroll
    for (int i = 0; i < 8; i++) acc[i] = 0.f;

    for (int tap = 0; tap < 9; tap++) {
        for (int cc = 0; cc < 4; cc++) {       // 32-ci chunks
            __syncthreads();
            const float4* src = (const float4*)&g_dcnt[tap * 16384 + cc * 4096];
            float4* dst = (float4*)w_s;
            #pragma unroll
            for (int i = 0; i < 4; i++) dst[tid + i * 256] = src[tid + i * 256];
            __syncthreads();
            const float* sp = &samp[pxl * 1153 + tap * 128 + cc * 32];
            #pragma unroll
            for (int ci = 0; ci < 32; ci++) {
                float s = sp[ci];
                float4 wa = *(float4*)&w_s[ci * 128 + co0];
                float4 wb = *(float4*)&w_s[ci * 128 + co0 + 4];
                acc[0] += s * wa.x; acc[1] += s * wa.y; acc[2] += s * wa.z; acc[3] += s * wa.w;
                acc[4] += s * wb.x; acc[5] += s * wb.y; acc[6] += s * wb.z; acc[7] += s * wb.w;
            }
        }
    }

    int rr = pxl >> 2, cl = pxl & 3;
    int y = ty * 4 + rr, x = tx * 4 + cl;
    float* o = &g_h2[((b * H + y) * W + x) * 128 + co0];
    float4 o0 = make_float4(acc[0] + dcn_b[co0+0], acc[1] + dcn_b[co0+1],
                            acc[2] + dcn_b[co0+2], acc[3] + dcn_b[co0+3]);
    float4 o1 = make_float4(acc[4] + dcn_b[co0+4], acc[5] + dcn_b[co0+5],
                            acc[6] + dcn_b[co0+6], acc[7] + dcn_b[co0+7]);
    *(float4*)&o[0] = o0;
    *(float4*)&o[4] = o1;
}

// ---------------------------------------------------------------------------
// BN stats: partial sums over 128-pixel slabs, per-channel atomics
// ---------------------------------------------------------------------------
__global__ void bn_stats_kernel() {
    int c = threadIdx.x;
    int p0 = blockIdx.x * 128;
    float s = 0.f, q = 0.f;
    for (int i = 0; i < 128; i++) {
        float v = g_h3[(p0 + i) * 128 + c];
        s += v; q += v * v;
    }
    atomicAdd(&g_sum[c], s);
    atomicAdd(&g_sq[c], q);
}

__global__ void bn_final_kernel(const float* __restrict__ gamma, const float* __restrict__ beta) {
    int c = threadIdx.x;
    float n = (float)NTOT;
    float mean = g_sum[c] / n;
    float var  = g_sq[c] / n - mean * mean;
    float sc = gamma[c] * rsqrtf(var + 1e-5f);
    g_scale[c] = sc;
    g_shift[c] = beta[c] - mean * sc;
}

__device__ __forceinline__ float gelu_exact(float v) {
    return 0.5f * v * (1.f + erff(v * 0.70710678118654752f));
}

// ---------------------------------------------------------------------------
// BN + GELU + NHWC->NCHW transpose into d_out (h part)
// ---------------------------------------------------------------------------
__global__ void bn_gelu_out_kernel(float* __restrict__ out) {
    __shared__ float s[64 * 129];
    int tid = threadIdx.x;
    int b = blockIdx.y;
    int p0 = blockIdx.x * 64;
    for (int idx = tid; idx < 64 * 128; idx += 256) {
        int p = idx >> 7, c = idx & 127;
        float v = g_h3[(b * NPIX + p0 + p) * 128 + c];
        v = v * g_scale[c] + g_shift[c];
        s[p * 129 + c] = gelu_exact(v);
    }
    __syncthreads();
    for (int idx = tid; idx < 64 * 128; idx += 256) {
        int c = idx >> 6, p = idx & 63;
        out[(b * 128 + c) * NPIX + p0 + p] = s[p * 129 + c];
    }
}

// ---------------------------------------------------------------------------
// Mask conv: 3x3, 128 -> 1, input = gelu(bn(h3)) computed on the fly.
// Tile 4x8 pixels, halo 6x10.
// ---------------------------------------------------------------------------
__global__ void mask_conv_kernel(const float* __restrict__ mw, const float* __restrict__ mb,
                                 float* __restrict__ outm) {
    __shared__ float g_s[60 * 129];
    __shared__ float wm[1152];
    __shared__ float red[32 * 9];
    int tid = threadIdx.x;
    int b = blockIdx.y;
    int ty = blockIdx.x / 7, tx = blockIdx.x % 7;
    int y0 = ty * 4 - 1, x0 = tx * 8 - 1;

    for (int idx = tid; idx < 60 * 128; idx += 256) {
        int px = idx >> 7, ci = idx & 127;
        int gy = y0 + px / 10, gx = x0 + px % 10;
        float v = 0.f;
        if (gy >= 0 && gy < H && gx >= 0 && gx < W) {
            v = g_h3[((b * H + gy) * W + gx) * 128 + ci];
            v = gelu_exact(v * g_scale[ci] + g_shift[ci]);
        }
        g_s[px * 129 + ci] = v;
    }
    for (int i = tid; i < 1152; i += 256) wm[i] = mw[i];
    __syncthreads();

    int px = tid & 31, q = tid >> 5;   // q: 8 groups of 16 ci
    int r = px >> 3, c = px & 7;
    float acc = 0.f;
    #pragma unroll
    for (int k = 0; k < 9; k++) {
        int hp = (r + k / 3) * 10 + c + k % 3;
        const float* gp = &g_s[hp * 129 + q * 16];
        #pragma unroll
        for (int ci = 0; ci < 16; ci++)
            acc += gp[ci] * wm[(q * 16 + ci) * 9 + k];
    }
    red[px * 9 + q] = acc;
    __syncthreads();
    if (tid < 32) {
        float s2 = 0.f;
        #pragma unroll
        for (int qq = 0; qq < 8; qq++) s2 += red[tid * 9 + qq];
        int gy = ty * 4 + (tid >> 3), gx = tx * 8 + (tid & 7);
        outm[b * NPIX + gy * W + gx] = s2 + mb[0];
    }
}

// ---------------------------------------------------------------------------
extern "C" void kernel_launch(void* const* d_in, const int* in_sizes, int n_in,
                              void* d_out, int out_size) {
    const float* x      = (const float*)d_in[0];
    const float* y      = (const float*)d_in[1];
    const float* conv_w = (const float*)d_in[2];
    const float* conv_b = (const float*)d_in[3];
    const float* off_w  = (const float*)d_in[4];
    const float* off_b  = (const float*)d_in[5];
    const float* dcn_w  = (const float*)d_in[6];
    const float* dcn_b  = (const float*)d_in[7];
    const float* conv2_w= (const float*)d_in[8];
    const float* conv2_b= (const float*)d_in[9];
    const float* bn_g   = (const float*)d_in[10];
    const float* bn_b   = (const float*)d_in[11];
    const float* mask_w = (const float*)d_in[12];
    const float* mask_b = (const float*)d_in[13];
    float* out = (float*)d_out;

    // idempotent; executes immediately (not a stream op) so capture-safe
    cudaFuncSetAttribute(deform_kernel, cudaFuncAttributeMaxDynamicSharedMemorySize,
                         DEF_SMEM_BYTES);

    prep_kernel<<<128, 256>>>(conv_w, off_w, conv2_w, dcn_w);
    transpose_in_kernel<<<dim3(49, 8), 256>>>(x, y);
    conv3x3_kernel<256, 64, 128, 128, 0, 1, 0><<<dim3(49, 2, 8), 256>>>(conv_b);
    conv3x3_kernel<128, 32, 32, 18, 1, 2, 1><<<dim3(49, 1, 8), 128>>>(off_b);
    deform_kernel<<<dim3(196, 1, 8), 256, DEF_SMEM_BYTES>>>(dcn_b);
    conv3x3_kernel<128, 64, 128, 128, 3, 4, 2><<<dim3(49, 2, 8), 256>>>(conv2_b);
    bn_stats_kernel<<<196, 128>>>();
    bn_final_kernel<<<1, 128>>>(bn_g, bn_b);
    bn_gelu_out_kernel<<<dim3(49, 8), 256>>>(out);
    mask_conv_kernel<<<dim3(98, 8), 256>>>(mask_w, mask_b, out + 8 * 128 * NPIX);
}